// round 4
// baseline (speedup 1.0000x reference)
#include <cuda_runtime.h>
#include <cuda_bf16.h>

// Problem shape (fixed by setup_inputs): B=8, H=96, W=256
// corr_i: (N, 1, 1, W>>i) fp32, flow: (B, 2, H, W) fp32
// out: (B, 4*K, H, W) fp32 with K = 9 taps (R = 4)

namespace {

constexpr int Bsz = 8;
constexpr int Hsz = 96;
constexpr int Wsz = 256;
constexpr int HW  = Hsz * Wsz;          // 24576
constexpr int N   = Bsz * HW;           // 196608
constexpr int R   = 4;
constexpr int K   = 2 * R + 1;          // 9
constexpr int C   = 4 * K;              // 36 output channels

__device__ __forceinline__ void lookup_level(
    const float* __restrict__ row,   // this pixel's corr row, length Wi
    int Wi,
    float d,                         // disp / 2^i
    float* __restrict__ outp)        // out + b*C*HW + r, channel-strided by HW
{
#pragma unroll
    for (int k = 0; k < K; ++k) {
        // Match reference exactly: x = dx + d in fp32, then floor / frac.
        float x  = (float)(k - R) + d;
        float x0 = floorf(x);
        float w  = x - x0;
        int i0 = (int)x0;
        int i1 = i0 + 1;
        float v0 = (i0 >= 0 && i0 < Wi) ? __ldg(row + i0) : 0.0f;
        float v1 = (i1 >= 0 && i1 < Wi) ? __ldg(row + i1) : 0.0f;
        outp[k * HW] = (1.0f - w) * v0 + w * v1;
    }
}

__global__ void __launch_bounds__(256)
corr_lookup_kernel(const float* __restrict__ c0,
                   const float* __restrict__ c1,
                   const float* __restrict__ c2,
                   const float* __restrict__ c3,
                   const float* __restrict__ flow,
                   float* __restrict__ out)
{
    int n = blockIdx.x * blockDim.x + threadIdx.x;
    if (n >= N) return;

    int b = n / HW;
    int r = n - b * HW;                  // h*W + w within the image

    // flow channel 0 (disparity) for this pixel
    float disp = __ldg(flow + (size_t)b * 2 * HW + r);

    float* outp = out + (size_t)b * C * HW + r;

    lookup_level(c0 + (size_t)n * (Wsz >> 0), Wsz >> 0, disp * 1.0f,    outp + 0 * K * HW);
    lookup_level(c1 + (size_t)n * (Wsz >> 1), Wsz >> 1, disp * 0.5f,    outp + 1 * K * HW);
    lookup_level(c2 + (size_t)n * (Wsz >> 2), Wsz >> 2, disp * 0.25f,   outp + 2 * K * HW);
    lookup_level(c3 + (size_t)n * (Wsz >> 3), Wsz >> 3, disp * 0.125f,  outp + 3 * K * HW);
}

} // namespace

extern "C" void kernel_launch(void* const* d_in, const int* in_sizes, int n_in,
                              void* d_out, int out_size)
{
    const float* c0   = (const float*)d_in[0];
    const float* c1   = (const float*)d_in[1];
    const float* c2   = (const float*)d_in[2];
    const float* c3   = (const float*)d_in[3];
    const float* flow = (const float*)d_in[4];
    float* out = (float*)d_out;

    constexpr int TPB = 256;
    int blocks = (N + TPB - 1) / TPB;   // 768
    corr_lookup_kernel<<<blocks, TPB>>>(c0, c1, c2, c3, flow, out);
}

// round 5
// speedup vs baseline: 1.2175x; 1.2175x over previous
#include <cuda_runtime.h>
#include <cuda_bf16.h>

// Problem shape (fixed by setup_inputs): B=8, H=96, W=256
// corr_i: (N, 1, 1, W>>i) fp32, flow: (B, 2, H, W) fp32
// out: (B, 4*K, H, W) fp32 with K = 9 taps (R = 4)

namespace {

constexpr int Bsz = 8;
constexpr int Hsz = 96;
constexpr int Wsz = 256;
constexpr int HW  = Hsz * Wsz;          // 24576
constexpr int N   = Bsz * HW;           // 196608
constexpr int R   = 4;
constexpr int K   = 2 * R + 1;          // 9
constexpr int C   = 4 * K;              // 36 output channels

// One level: all 9 taps share the interp weight w = d - floor(d) and read a
// contiguous 10-float window V[base .. base+9], base = floor(d) - R.
// out_k = (1-w)*V[k] + w*V[k+1].  (Per-tap floor differs from this only within
// ~1 ulp of integer x; interpolation is continuous there, so output diff ~ulp.)
__device__ __forceinline__ void lookup_level(
    const float* __restrict__ row,   // this pixel's corr row, length Wi
    int Wi,
    float d,                         // disp / 2^i  in [0, Wi)
    float* __restrict__ outp)        // channel-strided by HW
{
    float fd = floorf(d);
    float w  = d - fd;
    int base = (int)fd - R;

    float v[K + 1];
#pragma unroll
    for (int j = 0; j <= K; ++j) {
        int idx = base + j;
        v[j] = (idx >= 0 && idx < Wi) ? __ldg(row + idx) : 0.0f;
    }

    float omw = 1.0f - w;
#pragma unroll
    for (int k = 0; k < K; ++k) {
        outp[k * HW] = omw * v[k] + w * v[k + 1];
    }
}

__global__ void __launch_bounds__(256)
corr_lookup_kernel(const float* __restrict__ c0,
                   const float* __restrict__ c1,
                   const float* __restrict__ c2,
                   const float* __restrict__ c3,
                   const float* __restrict__ flow,
                   float* __restrict__ out)
{
    int n = blockIdx.x * blockDim.x + threadIdx.x;
    if (n >= N) return;

    int b = n / HW;
    int r = n - b * HW;                  // h*W + w within the image

    // flow channel 0 (disparity) for this pixel
    float disp = __ldg(flow + (size_t)b * 2 * HW + r);

    float* outp = out + (size_t)b * C * HW + r;

    lookup_level(c0 + (size_t)n * (Wsz >> 0), Wsz >> 0, disp * 1.0f,   outp + 0 * K * HW);
    lookup_level(c1 + (size_t)n * (Wsz >> 1), Wsz >> 1, disp * 0.5f,   outp + 1 * K * HW);
    lookup_level(c2 + (size_t)n * (Wsz >> 2), Wsz >> 2, disp * 0.25f,  outp + 2 * K * HW);
    lookup_level(c3 + (size_t)n * (Wsz >> 3), Wsz >> 3, disp * 0.125f, outp + 3 * K * HW);
}

} // namespace

extern "C" void kernel_launch(void* const* d_in, const int* in_sizes, int n_in,
                              void* d_out, int out_size)
{
    const float* c0   = (const float*)d_in[0];
    const float* c1   = (const float*)d_in[1];
    const float* c2   = (const float*)d_in[2];
    const float* c3   = (const float*)d_in[3];
    const float* flow = (const float*)d_in[4];
    float* out = (float*)d_out;

    constexpr int TPB = 256;
    int blocks = (N + TPB - 1) / TPB;   // 768
    corr_lookup_kernel<<<blocks, TPB>>>(c0, c1, c2, c3, flow, out);
}

// round 6
// speedup vs baseline: 1.3161x; 1.0810x over previous
#include <cuda_runtime.h>
#include <cuda_bf16.h>

// Problem shape (fixed by setup_inputs): B=8, H=96, W=256
// corr_i: (N, 1, 1, W>>i) fp32, flow: (B, 2, H, W) fp32
// out: (B, 4*K, H, W) fp32 with K = 9 taps (R = 4)

namespace {

constexpr int Bsz = 8;
constexpr int Hsz = 96;
constexpr int Wsz = 256;
constexpr int HW  = Hsz * Wsz;          // 24576
constexpr int N   = Bsz * HW;           // 196608
constexpr int R   = 4;
constexpr int K   = 2 * R + 1;          // 9
constexpr int C   = 4 * K;              // 36 output channels

__global__ void __launch_bounds__(128)
corr_lookup_kernel(const float* __restrict__ c0,
                   const float* __restrict__ c1,
                   const float* __restrict__ c2,
                   const float* __restrict__ c3,
                   const float* __restrict__ flow,
                   float* __restrict__ out)
{
    int n = blockIdx.x * blockDim.x + threadIdx.x;
    if (n >= N) return;

    int b = n / HW;
    int r = n - b * HW;                  // h*W + w within the image

    // flow channel 0 (disparity) for this pixel
    float disp = __ldg(flow + (size_t)b * 2 * HW + r);

    // Per-level window parameters. All 9 taps of a level share interp weight
    // w = d - floor(d) and read contiguous window V[base .. base+9],
    // base = floor(d) - R. out_k = (1-w)*V[k] + w*V[k+1].
    const float* rows[4] = {
        c0 + (size_t)n * (Wsz >> 0),
        c1 + (size_t)n * (Wsz >> 1),
        c2 + (size_t)n * (Wsz >> 2),
        c3 + (size_t)n * (Wsz >> 3),
    };

    float wgt[4];
    int   base[4];
    float v[4][K + 1];

    // Phase 1: compute bases and issue ALL window loads up front (max MLP).
#pragma unroll
    for (int i = 0; i < 4; ++i) {
        float d  = disp * (1.0f / (float)(1 << i));
        float fd = floorf(d);
        wgt[i]   = d - fd;
        base[i]  = (int)fd - R;
        int Wi   = Wsz >> i;
        const float* row = rows[i];
        int bs = base[i];
#pragma unroll
        for (int j = 0; j <= K; ++j) {
            int idx = bs + j;
            v[i][j] = (idx >= 0 && idx < Wi) ? __ldcs(row + idx) : 0.0f;
        }
    }

    // Phase 2: interpolate and store (streaming: outputs have no reuse).
    float* outp = out + (size_t)b * C * HW + r;
#pragma unroll
    for (int i = 0; i < 4; ++i) {
        float w   = wgt[i];
        float omw = 1.0f - w;
#pragma unroll
        for (int k = 0; k < K; ++k) {
            __stcs(outp + (i * K + k) * HW, omw * v[i][k] + w * v[i][k + 1]);
        }
    }
}

} // namespace

extern "C" void kernel_launch(void* const* d_in, const int* in_sizes, int n_in,
                              void* d_out, int out_size)
{
    const float* c0   = (const float*)d_in[0];
    const float* c1   = (const float*)d_in[1];
    const float* c2   = (const float*)d_in[2];
    const float* c3   = (const float*)d_in[3];
    const float* flow = (const float*)d_in[4];
    float* out = (float*)d_out;

    constexpr int TPB = 128;
    int blocks = (N + TPB - 1) / TPB;   // 1536
    corr_lookup_kernel<<<blocks, TPB>>>(c0, c1, c2, c3, flow, out);
}